// round 8
// baseline (speedup 1.0000x reference)
#include <cuda_runtime.h>
#include <cstdint>

// Problem constants
#define NN   65536
#define KCH  8
#define HH   128
#define TT   4

// ---------------- device scratch (allocation-free rule) ----------------
__device__ float g_hsum[NN * HH];          // 32 MB per-node child-sum
__device__ int   g_perm[TT * NN];
__device__ int   g_cnt[TT];
// Pre-swizzled bf16 U^T tiles (hi/lo split): tile = 128 rows x 128 k bf16 = 32KB = 2048 uint4
__device__ uint4 g_Ufhi[TT * 2048];
__device__ uint4 g_Uflo[TT * 2048];
__device__ uint4 g_Uihi[TT * 3 * 2048];
__device__ uint4 g_Uilo[TT * 3 * 2048];

// smem tile layout (byte offsets from 1024-aligned base)
#define BHI_OFF 0
#define BLO_OFF 32768
#define AHI_OFF 65536
#define ALO_OFF 98304
#define SMEM_DYN (131072 + 1024)

// ---------------- helpers ----------------
__device__ __forceinline__ uint32_t smem_u32(const void* p) {
    uint32_t a;
    asm("{ .reg .u64 t; cvta.to.shared.u64 t, %1; cvt.u32.u64 %0, t; }" : "=r"(a) : "l"(p));
    return a;
}
__device__ __forceinline__ void ldsm_x4(uint32_t* r, uint32_t addr) {
    asm volatile("ldmatrix.sync.aligned.m8n8.x4.shared.b16 {%0,%1,%2,%3}, [%4];"
        : "=r"(r[0]), "=r"(r[1]), "=r"(r[2]), "=r"(r[3]) : "r"(addr));
}
__device__ __forceinline__ void ldsm_x2(uint32_t* r, uint32_t addr) {
    asm volatile("ldmatrix.sync.aligned.m8n8.x2.shared.b16 {%0,%1}, [%2];"
        : "=r"(r[0]), "=r"(r[1]) : "r"(addr));
}
__device__ __forceinline__ void mma_bf16(float* d, const uint32_t* a, const uint32_t* b) {
    asm volatile("mma.sync.aligned.m16n8k16.row.col.f32.bf16.bf16.f32 "
        "{%0,%1,%2,%3}, {%4,%5,%6,%7}, {%8,%9}, {%0,%1,%2,%3};"
        : "+f"(d[0]), "+f"(d[1]), "+f"(d[2]), "+f"(d[3])
        : "r"(a[0]), "r"(a[1]), "r"(a[2]), "r"(a[3]), "r"(b[0]), "r"(b[1]));
}

// fp32 -> (hi, lo) bf16 split via truncation
__device__ __forceinline__ uint32_t hi2(float a, float b) {
    return __byte_perm(__float_as_uint(a), __float_as_uint(b), 0x7632);
}
__device__ __forceinline__ float flo(float x) {
    return x - __uint_as_float(__float_as_uint(x) & 0xFFFF0000u);
}
__device__ __forceinline__ uint4 pack_hi8(float4 a, float4 b) {
    uint4 r; r.x = hi2(a.x, a.y); r.y = hi2(a.z, a.w); r.z = hi2(b.x, b.y); r.w = hi2(b.z, b.w);
    return r;
}
__device__ __forceinline__ uint4 pack_lo8(float4 a, float4 b) {
    uint4 r;
    r.x = hi2(flo(a.x), flo(a.y)); r.y = hi2(flo(a.z), flo(a.w));
    r.z = hi2(flo(b.x), flo(b.y)); r.w = hi2(flo(b.z), flo(b.w));
    return r;
}
__device__ __forceinline__ float sigmoidf_(float x) {
    return __fdividef(1.f, 1.f + __expf(-x));
}

// Swizzled byte offset inside a [128 rows][128 k] bf16 tile (256B rows, 16B chunks).
// chunk = k/8 (0..15); XOR low3 of chunk with row&7 -> ldmatrix conflict-free.
__device__ __forceinline__ uint32_t sw_off(int row, int chunk) {
    return (uint32_t)(row * 256 + ((chunk ^ (row & 7)) << 4));
}

// ---------------------------------------------------------------------------
__global__ void k_zero() { if (threadIdx.x < TT) g_cnt[threadIdx.x] = 0; }

__global__ void k_scatter(const int* __restrict__ type_id) {
    __shared__ int s_cnt[TT], s_base[TT], s_cur[TT];
    int tid = threadIdx.x;
    int n = blockIdx.x * 256 + tid;
    if (tid < TT) s_cnt[tid] = 0;
    __syncthreads();
    int t = type_id[n];
    atomicAdd(&s_cnt[t], 1);
    __syncthreads();
    if (tid < TT) { s_base[tid] = atomicAdd(&g_cnt[tid], s_cnt[tid]); s_cur[tid] = 0; }
    __syncthreads();
    int pos = atomicAdd(&s_cur[t], 1);
    g_perm[t * NN + s_base[t] + pos] = n;
}

// Prep: U_f^T tiles (row j, k contiguous), pre-swizzled, bf16 hi/lo
__global__ void k_prepUf(const float* __restrict__ U_f) {
    int idx = blockIdx.x * 256 + threadIdx.x;     // 4*2048 = 8192
    int t = idx >> 11, r = idx & 2047;
    int jj = r >> 4, ch = r & 15, k8 = ch * 8;
    float v[8];
#pragma unroll
    for (int kk = 0; kk < 8; ++kk) v[kk] = U_f[t * 16384 + (k8 + kk) * 128 + jj];
    float4 a = make_float4(v[0], v[1], v[2], v[3]);
    float4 b = make_float4(v[4], v[5], v[6], v[7]);
    uint32_t o = sw_off(jj, ch) >> 4;
    g_Ufhi[t * 2048 + o] = pack_hi8(a, b);
    g_Uflo[t * 2048 + o] = pack_lo8(a, b);
}

// Prep: U_iou^T tiles per (type, chunk)
__global__ void k_prepUi(const float* __restrict__ U_iou) {
    int idx = blockIdx.x * 256 + threadIdx.x;     // 12*2048 = 24576
    int tile = idx >> 11, r = idx & 2047;
    int t = tile / 3, cc = tile % 3;
    int jj = r >> 4, ch = r & 15, k8 = ch * 8;
    float v[8];
#pragma unroll
    for (int kk = 0; kk < 8; ++kk)
        v[kk] = U_iou[t * 49152 + (k8 + kk) * 384 + cc * 128 + jj];
    float4 a = make_float4(v[0], v[1], v[2], v[3]);
    float4 b = make_float4(v[4], v[5], v[6], v[7]);
    uint32_t o = sw_off(jj, ch) >> 4;
    g_Uihi[tile * 2048 + o] = pack_hi8(a, b);
    g_Uilo[tile * 2048 + o] = pack_lo8(a, b);
}

// ---------------------------------------------------------------------------
// Shared GEMM core: D[j, m] += A[j, k] * B[m, k]^T over 128x128x128, 3-way
// bf16 split; warp (w) owns j in [(w&3)*32, +32), m in [(w>>2)*64, +64).
// acc[t][i][q]: t = j-subtile (16), i = m-subtile (8), q = mma D frag.
// ---------------------------------------------------------------------------
__device__ __forceinline__ void gemm_core(uint32_t sb, int wid, int lane,
                                          float acc[2][8][4]) {
    int j0 = (wid & 3) * 32, mr0 = (wid >> 2) * 64;
    uint32_t r7 = (uint32_t)(lane & 7);
    uint32_t ca = (uint32_t)(lane >> 4);          // A chunk offset (0/1)
    uint32_t cb = (uint32_t)((lane >> 3) & 1);    // B chunk offset (0/1)
    uint32_t rbA0 = (uint32_t)((j0 + (lane & 15)) * 256);
    uint32_t rbA1 = rbA0 + 16 * 256;
    uint32_t rbB[8];
#pragma unroll
    for (int i = 0; i < 8; ++i) rbB[i] = (uint32_t)((mr0 + 8 * i + (lane & 7)) * 256);

    const uint32_t Ab[3] = { sb + AHI_OFF, sb + AHI_OFF, sb + ALO_OFF };
    const uint32_t Bb[3] = { sb + BHI_OFF, sb + BLO_OFF, sb + BHI_OFF };

#pragma unroll 1
    for (int sp = 0; sp < 3; ++sp) {
        uint32_t Abase = Ab[sp], Bbase = Bb[sp];
#pragma unroll
        for (int s = 0; s < 8; ++s) {
            uint32_t a[2][4];
            ldsm_x4(a[0], Abase + rbA0 + (((2 * s + ca) ^ r7) << 4));
            ldsm_x4(a[1], Abase + rbA1 + (((2 * s + ca) ^ r7) << 4));
            uint32_t b[8][2];
#pragma unroll
            for (int i = 0; i < 8; ++i)
                ldsm_x2(b[i], Bbase + rbB[i] + (((2 * s + cb) ^ r7) << 4));
#pragma unroll
            for (int t = 0; t < 2; ++t)
#pragma unroll
                for (int i = 0; i < 8; ++i)
                    mma_bf16(acc[t][i], a[t], b[i]);
        }
    }
}

// ---------------------------------------------------------------------------
// k_fgate: 16 nodes/CTA. B rows = node_local*8 + child (gathered h rows);
// A = U_f^T. Fused sigmoid + f*c child reduction; also emits g_hsum.
// ---------------------------------------------------------------------------
__global__ __launch_bounds__(256, 1)
void k_fgate(const float* __restrict__ h, const float* __restrict__ c,
             const float* __restrict__ f_input, const float* __restrict__ b_f,
             float* __restrict__ out) {
    int t = blockIdx.z;
    int cnt = g_cnt[t];
    int m0 = blockIdx.x * 16;
    if (m0 >= cnt) return;

    extern __shared__ char dsm[];
    uint32_t raw = smem_u32(dsm);
    uint32_t sb = (raw + 1023) & ~1023u;
    char* p = dsm + (sb - raw);

    int tid = threadIdx.x, wid = tid >> 5, lane = tid & 31;
    const int* perm = g_perm + t * NN + m0;

    // copy pre-swizzled U_f tiles (L2-resident)
    {
        const uint4* shi = g_Ufhi + t * 2048;
        const uint4* slo = g_Uflo + t * 2048;
        uint4* dhi = (uint4*)(p + AHI_OFF);
        uint4* dlo = (uint4*)(p + ALO_OFF);
        for (int i = tid; i < 2048; i += 256) { dhi[i] = shi[i]; dlo[i] = slo[i]; }
    }
    // stage H rows (row = ln*8 + k), 2 threads/row
    {
        int row = tid >> 1, half = tid & 1;
        int ln = row >> 3, k = row & 7;
        bool valid = (m0 + ln) < cnt;
        const float* hr = valid ? (h + (size_t)perm[ln] * 1024 + k * 128 + half * 64) : h;
#pragma unroll
        for (int g = 0; g < 8; ++g) {
            float4 a = make_float4(0.f, 0.f, 0.f, 0.f), b = a;
            if (valid) { a = *(const float4*)(hr + g * 8); b = *(const float4*)(hr + g * 8 + 4); }
            uint32_t o = sw_off(row, half * 8 + g);
            *(uint4*)(p + BHI_OFF + o) = pack_hi8(a, b);
            *(uint4*)(p + BLO_OFF + o) = pack_lo8(a, b);
        }
    }
    // h_sum for this tile's 16 nodes (rows L1-hot from staging)
    {
        int ln2 = tid >> 4, cb2 = (tid & 15) * 8;
        if (m0 + ln2 < cnt) {
            int n2 = perm[ln2];
            const float* hb = h + (size_t)n2 * 1024 + cb2;
            float4 s0 = *(const float4*)(hb);
            float4 s1 = *(const float4*)(hb + 4);
#pragma unroll
            for (int k = 1; k < KCH; ++k) {
                float4 v0 = *(const float4*)(hb + k * 128);
                float4 v1 = *(const float4*)(hb + k * 128 + 4);
                s0.x += v0.x; s0.y += v0.y; s0.z += v0.z; s0.w += v0.w;
                s1.x += v1.x; s1.y += v1.y; s1.z += v1.z; s1.w += v1.w;
            }
            *(float4*)(g_hsum + (size_t)n2 * 128 + cb2)     = s0;
            *(float4*)(g_hsum + (size_t)n2 * 128 + cb2 + 4) = s1;
        }
    }
    __syncthreads();

    float acc[2][8][4];
#pragma unroll
    for (int a_ = 0; a_ < 2; ++a_)
#pragma unroll
        for (int i = 0; i < 8; ++i)
#pragma unroll
            for (int q = 0; q < 4; ++q) acc[a_][i][q] = 0.f;

    gemm_core(sb, wid, lane, acc);

    // Epilogue. Thread holds: j = j0 + 16t + 8rh + lane/4; children 2c, 2c+1
    // (c = lane&3) of node i0 + i. Reduce over children via 2 shfl_xor.
    int j0 = (wid & 3) * 32, i0 = (wid >> 2) * 8;
    int lane4 = lane >> 2, c2 = (lane & 3) * 2;
#pragma unroll
    for (int tt_ = 0; tt_ < 2; ++tt_) {
#pragma unroll
        for (int rh = 0; rh < 2; ++rh) {
            int j = j0 + 16 * tt_ + 8 * rh + lane4;
            float bf = b_f[t * 128 + j];
#pragma unroll
            for (int i = 0; i < 8; ++i) {
                int li = i0 + i;
                if (m0 + li >= cnt) continue;           // uniform across warp
                int n = perm[li];
                float fin = f_input[(size_t)n * 128 + j];
                float d0 = acc[tt_][i][2 * rh + 0];
                float d1 = acc[tt_][i][2 * rh + 1];
                float cv0 = c[(size_t)n * 1024 + (size_t)c2 * 128 + j];
                float cv1 = c[(size_t)n * 1024 + (size_t)(c2 + 1) * 128 + j];
                float v = cv0 * sigmoidf_(d0 + fin + bf) + cv1 * sigmoidf_(d1 + fin + bf);
                v += __shfl_xor_sync(0xFFFFFFFFu, v, 1);
                v += __shfl_xor_sync(0xFFFFFFFFu, v, 2);
                if ((lane & 3) == 0) out[(size_t)n * 512 + 384 + j] = v;
            }
        }
    }
}

// ---------------------------------------------------------------------------
// k_iou: 128 nodes/CTA x 128-col chunk. B rows = gathered hsum; A = U_iou^T.
// ---------------------------------------------------------------------------
__global__ __launch_bounds__(256, 1)
void k_iou(const float* __restrict__ b_iou, float* __restrict__ out) {
    int t = blockIdx.z;
    int cnt = g_cnt[t];
    int m0 = blockIdx.x * 128;
    if (m0 >= cnt) return;
    int chunk = blockIdx.y;

    extern __shared__ char dsm[];
    uint32_t raw = smem_u32(dsm);
    uint32_t sb = (raw + 1023) & ~1023u;
    char* p = dsm + (sb - raw);

    int tid = threadIdx.x, wid = tid >> 5, lane = tid & 31;
    const int* perm = g_perm + t * NN + m0;

    {
        int tile = t * 3 + chunk;
        const uint4* shi = g_Uihi + tile * 2048;
        const uint4* slo = g_Uilo + tile * 2048;
        uint4* dhi = (uint4*)(p + AHI_OFF);
        uint4* dlo = (uint4*)(p + ALO_OFF);
        for (int i = tid; i < 2048; i += 256) { dhi[i] = shi[i]; dlo[i] = slo[i]; }
    }
    // stage hsum rows
    {
        int row = tid >> 1, half = tid & 1;
        bool valid = (m0 + row) < cnt;
        const float* hr = valid ? (g_hsum + (size_t)perm[row] * 128 + half * 64) : g_hsum;
#pragma unroll
        for (int g = 0; g < 8; ++g) {
            float4 a = make_float4(0.f, 0.f, 0.f, 0.f), b = a;
            if (valid) { a = *(const float4*)(hr + g * 8); b = *(const float4*)(hr + g * 8 + 4); }
            uint32_t o = sw_off(row, half * 8 + g);
            *(uint4*)(p + BHI_OFF + o) = pack_hi8(a, b);
            *(uint4*)(p + BLO_OFF + o) = pack_lo8(a, b);
        }
    }
    __syncthreads();

    float acc[2][8][4];
#pragma unroll
    for (int a_ = 0; a_ < 2; ++a_)
#pragma unroll
        for (int i = 0; i < 8; ++i)
#pragma unroll
            for (int q = 0; q < 4; ++q) acc[a_][i][q] = 0.f;

    gemm_core(sb, wid, lane, acc);

    // Epilogue: D[j, m] + bias -> out[perm[m]][chunk*128 + j]
    int j0 = (wid & 3) * 32, mr0 = (wid >> 2) * 64;
    int lane4 = lane >> 2, c2 = (lane & 3) * 2;
#pragma unroll
    for (int tt_ = 0; tt_ < 2; ++tt_) {
#pragma unroll
        for (int rh = 0; rh < 2; ++rh) {
            int j = j0 + 16 * tt_ + 8 * rh + lane4;
            float bi = b_iou[t * 384 + chunk * 128 + j];
#pragma unroll
            for (int i = 0; i < 8; ++i) {
#pragma unroll
                for (int o = 0; o < 2; ++o) {
                    int m = mr0 + 8 * i + c2 + o;
                    if (m0 + m < cnt) {
                        int n = perm[m];
                        out[(size_t)n * 512 + chunk * 128 + j] =
                            acc[tt_][i][2 * rh + o] + bi;
                    }
                }
            }
        }
    }
}

// ---------------------------------------------------------------------------
extern "C" void kernel_launch(void* const* d_in, const int* in_sizes, int n_in,
                              void* d_out, int out_size) {
    const float* h       = (const float*)d_in[0];
    const float* c       = (const float*)d_in[1];
    const float* f_input = (const float*)d_in[2];
    const int*   type_id = (const int*)d_in[3];
    const float* U_iou   = (const float*)d_in[4];
    const float* b_iou   = (const float*)d_in[5];
    const float* U_f     = (const float*)d_in[6];
    const float* b_f     = (const float*)d_in[7];
    float* out = (float*)d_out;

    cudaFuncSetAttribute(k_fgate, cudaFuncAttributeMaxDynamicSharedMemorySize, SMEM_DYN);
    cudaFuncSetAttribute(k_iou,   cudaFuncAttributeMaxDynamicSharedMemorySize, SMEM_DYN);

    k_zero<<<1, 32>>>();
    k_scatter<<<NN / 256, 256>>>(type_id);
    k_prepUf<<<32, 256>>>(U_f);
    k_prepUi<<<96, 256>>>(U_iou);
    // fgate first: it also produces g_hsum consumed by k_iou
    k_fgate<<<dim3(NN / 16, 1, TT), 256, SMEM_DYN>>>(h, c, f_input, b_f, out);
    k_iou<<<dim3(NN / 128, 3, TT), 256, SMEM_DYN>>>(b_iou, out);
}